// round 6
// baseline (speedup 1.0000x reference)
#include <cuda_runtime.h>
#include <math.h>

// TwoLayerNetwork: ConstantCurrentLIFEncoder -> LIFCell -> LILinearCell, T=32,
// then max over timesteps and log_softmax.
//
// Constants: DT*TAU_MEM_INV = 0.1 (decay 0.9), DT*TAU_SYN_INV = 0.2 (decay 0.8),
// V_TH = 1.0.
//
// EXACT fast path (proof): v_enc follows v' = 0.9 v + 0.1 x from 0, so
// v_enc <= max_j x_j for all t. A spike needs v_enc > 1.0, so if ALL pixels of
// a row are <= 1.0 that row never spikes downstream: v_out stays 0 and the
// answer is log_softmax(zeros) = -log(10).
//
// R6 layout: each warp owns TWO rows, scanned as one contiguous 392-float4
// span (12-13 vec4 loads per lane -> 6KB in flight per warp). Hotness is
// tested per PAIR: if the pair contains any pixel > 1.0, BOTH rows run the
// full simulator. This is exact because the simulator is itself exact for
// cold rows (no spikes -> v_out = 0 -> -log 10). Grid 512x128 = one wave.

#define NT 32
#define NPL 25   // neurons per lane (25*32 = 800 >= 784)

__device__ __forceinline__ void simulate_row(
    const float* __restrict__ x,       // row base, 784 floats
    const float* __restrict__ W,       // [10, 784]
    float* __restrict__ orow,          // out row base, 10 floats
    const int lane)
{
    float xs[NPL], ve[NPL], v0[NPL], i0[NPL];
#pragma unroll
    for (int i = 0; i < NPL; i++) {
        const int j = lane + 32 * i;
        xs[i] = (j < 784) ? 0.1f * __ldg(&x[j]) : 0.0f;
        ve[i] = 0.0f; v0[i] = 0.0f; i0[i] = 0.0f;
    }

    float v_out = 0.0f, i_out = 0.0f, vmax = -INFINITY;

#pragma unroll 1
    for (int t = 0; t < NT; t++) {
        unsigned tmask = 0u;
#pragma unroll
        for (int i = 0; i < NPL; i++) {
            // encoder LIF step
            float v = fmaf(ve[i], 0.9f, xs[i]);
            const bool pe = (v > 1.0f);
            const float zef = pe ? 1.0f : 0.0f;
            ve[i] = pe ? 0.0f : v;
            // hidden LIF step (reads old v0, i0)
            const float vd = fmaf(v0[i], 0.9f, 0.1f * i0[i]);
            const bool p0 = (vd > 1.0f);
            v0[i] = p0 ? 0.0f : vd;
            i0[i] = fmaf(i0[i], 0.8f, zef);
            if (p0) tmask |= (1u << i);
        }

        // s[k] = sum_j z0[j] * W[k, j]; zero on spike-free steps.
        float s = 0.0f;
        if (__any_sync(0xffffffffu, tmask != 0u)) {
            float acc[10];
#pragma unroll
            for (int k = 0; k < 10; k++) acc[k] = 0.0f;
            unsigned mm = tmask;
            while (mm) {
                const int i = __ffs(mm) - 1;
                mm &= (mm - 1u);
                const int j = lane + 32 * i;
#pragma unroll
                for (int k = 0; k < 10; k++)
                    acc[k] += __ldg(&W[k * 784 + j]);
            }
#pragma unroll
            for (int k = 0; k < 10; k++) {
#pragma unroll
                for (int off = 16; off; off >>= 1)
                    acc[k] += __shfl_xor_sync(0xffffffffu, acc[k], off);
            }
            s = acc[0];
#pragma unroll
            for (int k = 1; k < 10; k++) s = (lane == k) ? acc[k] : s;
        }

        const float i_jump = i_out + s;
        v_out = fmaf(v_out, 0.9f, 0.1f * i_jump);
        i_out = 0.8f * i_jump;
        vmax = fmaxf(vmax, v_out);
    }

    // log_softmax over the 10 classes held by lanes 0..9
    const float v = (lane < 10) ? vmax : -INFINITY;
    float mred = v;
#pragma unroll
    for (int off = 16; off; off >>= 1)
        mred = fmaxf(mred, __shfl_xor_sync(0xffffffffu, mred, off));
    float e = (lane < 10) ? expf(v - mred) : 0.0f;
    float se = e;
#pragma unroll
    for (int off = 16; off; off >>= 1)
        se += __shfl_xor_sync(0xffffffffu, se, off);

    if (lane < 10)
        orow[lane] = v - mred - logf(se);
}

__global__ __launch_bounds__(128) void snn_kernel(
    const float* __restrict__ image,   // [4096, 784]
    const float* __restrict__ W,       // [10, 784]
    float* __restrict__ out)           // [4096, 10]
{
    const int lane = threadIdx.x & 31;
    const int w = blockIdx.x * 4 + (threadIdx.x >> 5);   // warp id, 0..2047
    const int b0 = w * 2;                                // first of two rows

    // Unconditional early writes of the spike-free answer for both rows.
    // Hot pairs overwrite below in program order.
    if (lane < 10) {
        out[(size_t)b0 * 10 + lane]       = -2.302585093f;
        out[(size_t)(b0 + 1) * 10 + lane] = -2.302585093f;
    }

    // ---- vectorized pair-max scan: 392 contiguous float4 ----
    const float* x = image + (size_t)b0 * 784;
    const float4* x4 = (const float4*)x;   // 392 vec4 over the two rows

    float m = 0.0f;
#pragma unroll
    for (int i = 0; i < 12; i++) {
        const float4 v = __ldg(&x4[lane + 32 * i]);
        m = fmaxf(m, fmaxf(fmaxf(v.x, v.y), fmaxf(v.z, v.w)));
    }
    if (lane < 8) {   // 392 = 12*32 + 8
        const float4 v = __ldg(&x4[384 + lane]);
        m = fmaxf(m, fmaxf(fmaxf(v.x, v.y), fmaxf(v.z, v.w)));
    }

    // Pair provably spike-free -> constants already written, done.
    if (!__any_sync(0xffffffffu, m > 1.0f))
        return;

    // Hot pair (rare): run the exact simulator on BOTH rows. The simulator
    // is exact for cold rows too (yields -log 10), so pair granularity is safe.
    simulate_row(x,       W, out + (size_t)b0 * 10,       lane);
    simulate_row(x + 784, W, out + (size_t)(b0 + 1) * 10, lane);
}

extern "C" void kernel_launch(void* const* d_in, const int* in_sizes, int n_in,
                              void* d_out, int out_size) {
    const float* image = (const float*)d_in[0];  // [4096,1,28,28] fp32
    const float* W     = (const float*)d_in[1];  // [10,784] fp32
    float* out         = (float*)d_out;          // [4096,10] fp32
    (void)in_sizes; (void)n_in; (void)out_size;

    snn_kernel<<<512, 128>>>(image, W, out);
}